// round 3
// baseline (speedup 1.0000x reference)
#include <cuda_runtime.h>
#include <cuda_bf16.h>
#include <cstdint>

// ---------------- problem constants ----------------
#define DIM_B 4
#define DIM_N 1024
#define DIM_D 512
#define DIM_F 16
#define DIM_O 64
// out[b,n,f,o] = sum_d (x[b,n,d] + bias[idx[b,f],d]) * W[idx[b,f]][d,o]
//             = (X[b] @ Wcat[b])[n, f*64+o] + cbias[b,f,o]
// where Wcat[b][:, f*64+o] = W[idx[b,f]][:,o] and cbias is n-independent.

// ---------------- helpers ----------------
__device__ __forceinline__ uint32_t smem_u32(const void* p) {
    uint32_t a;
    asm("{ .reg .u64 t; cvta.to.shared.u64 t, %1; cvt.u32.u64 %0, t; }"
        : "=r"(a) : "l"(p));
    return a;
}

// fp32 -> tf32 round-to-nearest (unbiased; HW truncation would bias the K=512
// accumulation to ~1e-3 and risk the rel-err gate)
__device__ __forceinline__ uint32_t f32_to_tf32(float f) {
    uint32_t r;
    asm("cvt.rna.tf32.f32 %0, %1;" : "=r"(r) : "f"(f));
    return r;
}

__device__ __forceinline__ void cp_async16(uint32_t smem_dst, const void* gptr) {
    asm volatile("cp.async.cg.shared.global [%0], [%1], 16;"
                 :: "r"(smem_dst), "l"(gptr) : "memory");
}

__device__ __forceinline__ void mma_tf32(float& c0, float& c1, float& c2, float& c3,
                                         uint32_t a0, uint32_t a1, uint32_t a2, uint32_t a3,
                                         uint32_t b0, uint32_t b1) {
    asm volatile(
        "mma.sync.aligned.m16n8k8.row.col.f32.tf32.tf32.f32 "
        "{%0,%1,%2,%3}, {%4,%5,%6,%7}, {%8,%9}, {%0,%1,%2,%3};"
        : "+f"(c0), "+f"(c1), "+f"(c2), "+f"(c3)
        : "r"(a0), "r"(a1), "r"(a2), "r"(a3), "r"(b0), "r"(b1));
}

// ---------------- bias precompute ----------------
// cbias[p][o] = sum_d bias[idx[p]][d] * W[idx[p]][d][o]  (full fp32)
__device__ float g_cbias[DIM_B * DIM_F * DIM_O];

__global__ void __launch_bounds__(512) bias_kernel(
    const int* __restrict__ idx,
    const float* __restrict__ bias_tab,
    const float* __restrict__ w_tab)
{
    int p = blockIdx.x;                 // (b,f) pair 0..63
    int v = idx[p];
    int o = threadIdx.x & 63;
    int slice = threadIdx.x >> 6;       // 0..7, 64 d's each
    const float* bptr = bias_tab + (size_t)v * DIM_D;
    const float* wptr = w_tab + (size_t)v * DIM_D * DIM_O + o;
    float acc = 0.f;
    int d0 = slice * 64;
    #pragma unroll 8
    for (int d = d0; d < d0 + 64; ++d)
        acc += bptr[d] * wptr[(size_t)d * DIM_O];
    __shared__ float red[512];
    red[threadIdx.x] = acc;
    __syncthreads();
    if (slice == 0) {
        float s = 0.f;
        #pragma unroll
        for (int i = 0; i < 8; i++) s += red[o + i * 64];
        g_cbias[p * DIM_O + o] = s;
    }
}

// ---------------- main GEMM: mma.sync tf32, cp.async double-buffered ----------------
// CTA tile: M=128 (rows of x), N=128 (2 f's x 64 o), K=512 in chunks of 32.
// 8 warps as 4(m) x 2(n): warp tile 32 x 64.
static constexpr int KC = 32;
static constexpr int CHUNKS = DIM_D / KC;        // 16

// smem strides chosen for conflict-free mma fragment loads:
//  A [m][k]: row stride 36 floats (144 B, 16B-aligned; bank = 4m+k, distinct)
//  B [k][n]: row stride 136 floats (544 B, 16B-aligned; bank = 8k+n, distinct)
static constexpr int A_STRIDE = 36;                       // floats
static constexpr int B_STRIDE = 136;                      // floats
static constexpr int A_BYTES  = 128 * A_STRIDE * 4;       // 18432
static constexpr int B_BYTES  = KC * B_STRIDE * 4;        // 17408
static constexpr int STAGE_BYTES = A_BYTES + B_BYTES;     // 35840
static constexpr int SMEM_TOTAL  = 2 * STAGE_BYTES;       // 71680

__global__ void __launch_bounds__(256, 2) mm_kernel(
    const float* __restrict__ x,
    const int* __restrict__ idx,
    const float* __restrict__ w_tab,
    float* __restrict__ out)
{
    extern __shared__ char smem[];
    const uint32_t smem_base = smem_u32(smem);

    const int tid  = threadIdx.x;
    const int wid  = tid >> 5;
    const int lane = tid & 31;
    const int grp  = lane >> 2;         // 0..7
    const int tg   = lane & 3;          // 0..3

    const int mtile  = blockIdx.x;      // 0..7  (128 rows each)
    const int ntile  = blockIdx.y;      // 0..7  (128 cols = 2 f's)
    const int b      = blockIdx.z;      // 0..3
    const int f_base = ntile * 2;

    const int v0 = idx[b * DIM_F + f_base];
    const int v1 = idx[b * DIM_F + f_base + 1];

    const float* xbase = x + ((size_t)b * DIM_N + (size_t)mtile * 128) * DIM_D;
    const float* wb0 = w_tab + (size_t)v0 * DIM_D * DIM_O;
    const float* wb1 = w_tab + (size_t)v1 * DIM_D * DIM_O;

    // ---- per-thread load segments (4 x 16B for A, 4 x 16B for B per chunk)
    // A: seg = tid + 256*i : row = seg>>3 (0..127), c4 = seg&7 (8 x 16B per row)
    // B: seg = tid + 256*i : k = seg>>5 (0..31), s4 = seg&31 (32 x 16B per k-row)
    auto load_stage = [&](int stage, int k0) {
        uint32_t abase = smem_base + stage * STAGE_BYTES;
        uint32_t bbase = abase + A_BYTES;
        #pragma unroll
        for (int i = 0; i < 4; ++i) {
            int seg = tid + 256 * i;
            int row = seg >> 3, c4 = seg & 7;
            cp_async16(abase + row * (A_STRIDE * 4) + c4 * 16,
                       xbase + (size_t)row * DIM_D + k0 + c4 * 4);
        }
        #pragma unroll
        for (int i = 0; i < 4; ++i) {
            int seg = tid + 256 * i;
            int k = seg >> 5, s4 = seg & 31;
            const float* wsrc = (s4 < 16)
                ? wb0 + (size_t)(k0 + k) * DIM_O + s4 * 4
                : wb1 + (size_t)(k0 + k) * DIM_O + (s4 - 16) * 4;
            cp_async16(bbase + k * (B_STRIDE * 4) + s4 * 16, wsrc);
        }
    };

    // warp tile: 32(m) x 64(n);  2 m16-tiles x 8 n8-tiles
    const int warp_m = (wid >> 1) * 32;
    const int warp_n = (wid & 1) * 64;

    float acc[2][8][4];
    #pragma unroll
    for (int mt = 0; mt < 2; ++mt)
        #pragma unroll
        for (int nt = 0; nt < 8; ++nt)
            #pragma unroll
            for (int c = 0; c < 4; ++c) acc[mt][nt][c] = 0.f;

    // ---- pipeline
    load_stage(0, 0);
    asm volatile("cp.async.commit_group;" ::: "memory");

    for (int chunk = 0; chunk < CHUNKS; ++chunk) {
        const int stage = chunk & 1;
        if (chunk + 1 < CHUNKS) {
            load_stage((chunk + 1) & 1, (chunk + 1) * KC);
            asm volatile("cp.async.commit_group;" ::: "memory");
            asm volatile("cp.async.wait_group 1;" ::: "memory");
        } else {
            asm volatile("cp.async.wait_group 0;" ::: "memory");
        }
        __syncthreads();

        const float* As = reinterpret_cast<const float*>(smem + stage * STAGE_BYTES);
        const float* Bs = reinterpret_cast<const float*>(smem + stage * STAGE_BYTES + A_BYTES);

        #pragma unroll
        for (int s = 0; s < KC / 8; ++s) {
            const int ka = s * 8 + tg;
            // A fragments: rows warp_m + mt*16 + grp (+8), cols ka (+4)
            uint32_t afr[2][4];
            #pragma unroll
            for (int mt = 0; mt < 2; ++mt) {
                const float* ap = As + (warp_m + mt * 16 + grp) * A_STRIDE + ka;
                afr[mt][0] = f32_to_tf32(ap[0]);
                afr[mt][1] = f32_to_tf32(ap[8 * A_STRIDE]);
                afr[mt][2] = f32_to_tf32(ap[4]);
                afr[mt][3] = f32_to_tf32(ap[8 * A_STRIDE + 4]);
            }
            // B fragments: k rows ka (+4), col warp_n + nt*8 + grp
            uint32_t bfr[8][2];
            #pragma unroll
            for (int nt = 0; nt < 8; ++nt) {
                const float* bp = Bs + ka * B_STRIDE + warp_n + nt * 8 + grp;
                bfr[nt][0] = f32_to_tf32(bp[0]);
                bfr[nt][1] = f32_to_tf32(bp[4 * B_STRIDE]);
            }
            #pragma unroll
            for (int mt = 0; mt < 2; ++mt)
                #pragma unroll
                for (int nt = 0; nt < 8; ++nt)
                    mma_tf32(acc[mt][nt][0], acc[mt][nt][1], acc[mt][nt][2], acc[mt][nt][3],
                             afr[mt][0], afr[mt][1], afr[mt][2], afr[mt][3],
                             bfr[nt][0], bfr[nt][1]);
        }
        __syncthreads();
    }

    // ---- epilogue: add cbias (constant per output column), store float2
    // columns f_base*64 .. f_base*64+127 are contiguous in both cbias and out.
    const float* cbp = g_cbias + (b * DIM_F + f_base) * DIM_O;
    float2 cb[8];
    #pragma unroll
    for (int nt = 0; nt < 8; ++nt)
        cb[nt] = *reinterpret_cast<const float2*>(cbp + warp_n + nt * 8 + 2 * tg);

    #pragma unroll
    for (int mt = 0; mt < 2; ++mt) {
        #pragma unroll
        for (int r2 = 0; r2 < 2; ++r2) {
            int m_global = mtile * 128 + warp_m + mt * 16 + grp + r2 * 8;
            float* rowp = out + (((size_t)b * DIM_N + m_global) * DIM_F + f_base) * DIM_O;
            #pragma unroll
            for (int nt = 0; nt < 8; ++nt) {
                float2 ov;
                ov.x = acc[mt][nt][r2 * 2 + 0] + cb[nt].x;
                ov.y = acc[mt][nt][r2 * 2 + 1] + cb[nt].y;
                *reinterpret_cast<float2*>(rowp + warp_n + nt * 8 + 2 * tg) = ov;
            }
        }
    }
}

// ---------------- launch ----------------
extern "C" void kernel_launch(void* const* d_in, const int* in_sizes, int n_in,
                              void* d_out, int out_size) {
    const float* x        = (const float*)d_in[0];   // [4,1024,512] f32
    const int*   idx      = (const int*)d_in[1];     // [4,16] i32
    const float* bias_tab = (const float*)d_in[2];   // [64,512] f32
    const float* w_tab    = (const float*)d_in[3];   // [64, 512*64] f32
    float* out = (float*)d_out;                      // [4,1024,16,64] f32

    static bool attr_set = false;
    if (!attr_set) {
        cudaFuncSetAttribute(mm_kernel,
                             cudaFuncAttributeMaxDynamicSharedMemorySize, SMEM_TOTAL);
        attr_set = true;
    }

    bias_kernel<<<DIM_B * DIM_F, 512>>>(idx, bias_tab, w_tab);

    dim3 grid(DIM_N / 128, DIM_N / 128, DIM_B);      // (8 mtiles, 8 ntiles, 4 b)
    mm_kernel<<<grid, 256, SMEM_TOTAL>>>(x, idx, w_tab, out);
}